// round 12
// baseline (speedup 1.0000x reference)
#include <cuda_runtime.h>
#include <math.h>
#include <cstdint>

#define HH 128
#define WW 128
#define HW (HH*WW)
#define CC 64
#define OO 64
#define BB 4
#define KK 9
#define APAD 68   // words per A-row (68%32=4 -> conflict-free frag LDS; 272B rows, 16B aligned)

// Scratch (allocation-free rule: __device__ globals)
__device__ float4 g_wts[BB*KK*HW];        // per (b,k,pixel): 4 bilinear corner weights * mask
__device__ int4   g_offs[BB*KK*HW];       // per (b,k,pixel): 4 clamped corner plane-offsets
__device__ float  g_xm[(size_t)BB*HW*CC]; // x_main pixel-major [b][p][c]
__device__ float  g_wom[2*32*9*28];       // w_om pre-staged: [half][(cl*9+t)*28 + oc]
__device__ uint4  g_bfrag[KK*8*8*32];     // pre-packed B frags [k][kk][n][lane] = {bh0,bh1,bl0,bl1}

// ---- packed f32x2 helpers (offset conv) ----
__device__ __forceinline__ unsigned long long pk2(float lo, float hi) {
    unsigned long long r;
    asm("mov.b64 %0,{%1,%2};" : "=l"(r) : "f"(lo), "f"(hi));
    return r;
}
__device__ __forceinline__ void fma2(unsigned long long& d, unsigned long long a, unsigned long long b) {
    asm("fma.rn.f32x2 %0,%1,%2,%0;" : "+l"(d) : "l"(a), "l"(b));
}
__device__ __forceinline__ float2 up2(unsigned long long v) {
    float2 r;
    asm("mov.b64 {%0,%1},%2;" : "=f"(r.x), "=f"(r.y) : "l"(v));
    return r;
}
// ---- tf32 helpers ----
__device__ __forceinline__ uint32_t to_tf32(float v) {
    uint32_t r;
    asm("cvt.rna.tf32.f32 %0,%1;" : "=r"(r) : "f"(v));
    return r;
}
__device__ __forceinline__ void mma_tf32(float* d, const uint32_t* a, const uint32_t* b) {
    asm volatile(
        "mma.sync.aligned.m16n8k8.row.col.f32.tf32.tf32.f32 "
        "{%0,%1,%2,%3}, {%4,%5,%6,%7}, {%8,%9}, {%0,%1,%2,%3};"
        : "+f"(d[0]), "+f"(d[1]), "+f"(d[2]), "+f"(d[3])
        : "r"(a[0]), "r"(a[1]), "r"(a[2]), "r"(a[3]), "r"(b[0]), "r"(b[1]));
}

// ---------------- kernel 0a: pre-pack B fragments (tf32 hi/lo) ----------------
// g_bfrag[((k*8+kk)*8+n)*32 + lane] = {tf32(v0), tf32(v1), lo(v0), lo(v1)}
// where g=lane>>2, tig=lane&3, o=n*8+g, c0=kk*8+tig, c1=c0+4; v=weight[o][c][k].
__global__ void k_bfrag_prep(const float* __restrict__ w) {
    int i = blockIdx.x * 256 + threadIdx.x;
    if (i >= KK*8*8*32) return;
    int lane = i & 31;
    int n = (i >> 5) & 7;
    int kk = (i >> 8) & 7;
    int k = i >> 11;
    int g = lane >> 2, tig = lane & 3;
    int o = (n << 3) + g;
    int c0 = (kk << 3) + tig;
    int c1 = c0 + 4;
    float v0 = w[(o*CC + c0)*KK + k];
    float v1 = w[(o*CC + c1)*KK + k];
    uint4 f;
    f.x = to_tf32(v0);
    f.y = to_tf32(v1);
    f.z = to_tf32(v0 - __uint_as_float(f.x));
    f.w = to_tf32(v1 - __uint_as_float(f.y));
    g_bfrag[i] = f;
}

// ---------------- kernel 0a': w_om pre-stage into smem-ready layout ----------------
__global__ void k_wom_prep(const float* __restrict__ w_om) {
    int i = blockIdx.x * 256 + threadIdx.x;
    if (i >= 2*32*9*28) return;
    int half = i / (32*9*28);
    int r = i - half*(32*9*28);
    int ct = r / 28;
    int oc = r - ct*28;
    int cl = ct / 9;
    int t  = ct - cl*9;
    float v = 0.f;
    if (oc < 27) v = w_om[(oc*CC + (half*32 + cl))*KK + t];
    g_wom[i] = v;
}

// ---------------- kernel 0b: x_main transpose [C][H][W] -> [H][W][C] ----------------
__global__ __launch_bounds__(256) void k_xm_transpose(const float* __restrict__ x) {
    __shared__ float s[64*68];
    const int tid = threadIdx.x;
    const int b = blockIdx.y;
    const int p0 = blockIdx.x << 6;
#pragma unroll
    for (int i = 0; i < 4; i++) {
        int t = (i << 8) + tid;
        int c = t >> 4, p4 = t & 15;
        float4 v = *(const float4*)(x + (((size_t)b*CC + c) << 14) + p0 + (p4 << 2));
        int base = (p4 << 2)*68 + c;
        s[base] = v.x; s[base+68] = v.y; s[base+136] = v.z; s[base+204] = v.w;
    }
    __syncthreads();
#pragma unroll
    for (int i = 0; i < 4; i++) {
        int t = (i << 8) + tid;
        int p = t >> 4, c4 = t & 15;
        float4 v = *(const float4*)&s[p*68 + (c4 << 2)];
        *(float4*)(g_xm + (((size_t)b << 14) + p0 + p)*CC + (c4 << 2)) = v;
    }
}

// ---------------- kernel 1: offset-mask conv + bilinear prep (measured 84.7us) ----------------
__global__ __launch_bounds__(128) void k_offset3(
        const float* __restrict__ x_extra,
        const float* __restrict__ pre_offset,
        const float* __restrict__ pre_sim,
        const float* __restrict__ b_om) {
    __shared__ float ws[32*9*28];
    __shared__ float xt[4*18*20];
    const int tid = threadIdx.x;
    const int b = blockIdx.z;
    const int ty = tid >> 3;
    const int tx = tid & 7;
    const int h  = (blockIdx.y << 4) + ty;
    const int w0 = (blockIdx.x << 4) + (tx << 1);
    const int gy0 = (blockIdx.y << 4) - 1;
    const int gx0 = (blockIdx.x << 4) - 1;

    unsigned long long acc[2][14];
#pragma unroll
    for (int p = 0; p < 2; p++)
#pragma unroll
        for (int j = 0; j < 14; j++) acc[p][j] = 0ULL;

    const float* xb = x_extra + (size_t)b*CC*HW;

    for (int phase = 0; phase < 2; ++phase) {
        __syncthreads();
        {
            const float4* src = (const float4*)(g_wom + phase*(32*9*28));
            float4* dst = (float4*)ws;
            for (int i = tid; i < 32*9*28/4; i += 128) dst[i] = src[i];
        }
        __syncthreads();

        for (int rnd = 0; rnd < 8; ++rnd) {
            if (rnd) __syncthreads();
            for (int idx = tid; idx < 4*324; idx += 128) {
                int cc = idx / 324;
                int rem = idx - cc*324;
                int rr = rem / 18, col = rem - rr*18;
                int gy = gy0 + rr, gx = gx0 + col;
                int c = (phase << 5) + (rnd << 2) + cc;
                xt[cc*360 + rr*20 + col] = ((unsigned)gy < HH && (unsigned)gx < WW)
                    ? __ldg(xb + ((size_t)c << 14) + gy*WW + gx) : 0.f;
            }
            __syncthreads();

#pragma unroll
            for (int cl4 = 0; cl4 < 4; ++cl4) {
                const int cl = (rnd << 2) + cl4;
                float xp[3][4];
                const int base = cl4*360 + ty*20 + (tx << 1);
#pragma unroll
                for (int rr = 0; rr < 3; rr++) {
                    float2 lo = *(const float2*)&xt[base + rr*20];
                    float2 hi = *(const float2*)&xt[base + rr*20 + 2];
                    xp[rr][0] = lo.x; xp[rr][1] = lo.y; xp[rr][2] = hi.x; xp[rr][3] = hi.y;
                }
#pragma unroll
                for (int t = 0; t < 9; t++) {
                    const int tr = t/3, tc = t%3;
                    const ulonglong2* wr = (const ulonglong2*)&ws[(cl*9 + t)*28];
                    ulonglong2 q0 = wr[0], q1 = wr[1], q2 = wr[2];
                    ulonglong2 q3 = wr[3], q4 = wr[4], q5 = wr[5], q6 = wr[6];
                    unsigned long long xd0 = pk2(xp[tr][tc],     xp[tr][tc]);
                    unsigned long long xd1 = pk2(xp[tr][tc + 1], xp[tr][tc + 1]);
                    fma2(acc[0][0],  xd0, q0.x); fma2(acc[0][1],  xd0, q0.y);
                    fma2(acc[0][2],  xd0, q1.x); fma2(acc[0][3],  xd0, q1.y);
                    fma2(acc[0][4],  xd0, q2.x); fma2(acc[0][5],  xd0, q2.y);
                    fma2(acc[0][6],  xd0, q3.x); fma2(acc[0][7],  xd0, q3.y);
                    fma2(acc[0][8],  xd0, q4.x); fma2(acc[0][9],  xd0, q4.y);
                    fma2(acc[0][10], xd0, q5.x); fma2(acc[0][11], xd0, q5.y);
                    fma2(acc[0][12], xd0, q6.x); fma2(acc[0][13], xd0, q6.y);
                    fma2(acc[1][0],  xd1, q0.x); fma2(acc[1][1],  xd1, q0.y);
                    fma2(acc[1][2],  xd1, q1.x); fma2(acc[1][3],  xd1, q1.y);
                    fma2(acc[1][4],  xd1, q2.x); fma2(acc[1][5],  xd1, q2.y);
                    fma2(acc[1][6],  xd1, q3.x); fma2(acc[1][7],  xd1, q3.y);
                    fma2(acc[1][8],  xd1, q4.x); fma2(acc[1][9],  xd1, q4.y);
                    fma2(acc[1][10], xd1, q5.x); fma2(acc[1][11], xd1, q5.y);
                    fma2(acc[1][12], xd1, q6.x); fma2(acc[1][13], xd1, q6.y);
                }
            }
        }
    }

#pragma unroll
    for (int p = 0; p < 2; p++) {
        const int wp_ = w0 + p;
        const int pix = h*WW + wp_;
        float a[28];
#pragma unroll
        for (int j = 0; j < 14; j++) {
            float2 f = up2(acc[p][j]);
            a[2*j] = f.x; a[2*j+1] = f.y;
        }
#pragma unroll
        for (int k = 0; k < 9; k++) {
            float ry = a[2*k]   + __ldg(b_om + 2*k);
            float rx = a[2*k+1] + __ldg(b_om + 2*k + 1);
            float rm = a[18+k]  + __ldg(b_om + 18 + k);
            int gi = (b*KK + k)*HW + pix;
            float poy = __ldg(pre_offset + 2*gi + 1);
            float pox = __ldg(pre_offset + 2*gi + 0);
            float ps  = __ldg(pre_sim + gi);

            float py = 10.f*tanhf(ry) + poy + (float)(h - 1) + (float)(k/3);
            float px = 10.f*tanhf(rx) + pox + (float)(wp_ - 1) + (float)(k%3);
            float m  = 1.f / (1.f + expf(-(rm * ps)));

            float fy = floorf(py), fx = floorf(px);
            float dy = py - fy,   dx = px - fx;
            int iy0 = (int)fy, ix0 = (int)fx;
            int iy1 = iy0 + 1, ix1 = ix0 + 1;
            bool vy0 = (unsigned)iy0 < HH, vy1 = (unsigned)iy1 < HH;
            bool vx0 = (unsigned)ix0 < WW, vx1 = (unsigned)ix1 < WW;

            float w00 = (vy0 && vx0) ? (1.f-dy)*(1.f-dx)*m : 0.f;
            float w01 = (vy0 && vx1) ? (1.f-dy)*dx*m       : 0.f;
            float w10 = (vy1 && vx0) ? dy*(1.f-dx)*m       : 0.f;
            float w11 = (vy1 && vx1) ? dy*dx*m             : 0.f;

            int cy0 = min(max(iy0, 0), HH-1), cy1 = min(max(iy1, 0), HH-1);
            int cx0 = min(max(ix0, 0), WW-1), cx1 = min(max(ix1, 0), WW-1);

            g_wts[gi]  = make_float4(w00, w01, w10, w11);
            g_offs[gi] = make_int4(cy0*WW + cx0, cy0*WW + cx1, cy1*WW + cx0, cy1*WW + cx1);
        }
    }
}

// ---------------- kernel 2: gather -> tf32 hi/lo smem -> mma.sync, 64-px tiles ----------------
// Block = 128 threads = 4 warps; tile = 64 px x 64 o; warp = 16 px (m16) x 64 o (8 n-tiles).
// B fragments pre-packed in gmem (coalesced LDG.128); wt/of via uniform __ldg.
#define SM_VH 0
#define SM_VL (SM_VH + 64*APAD*4)      // 17408
#define SM_SZ (SM_VL + 64*APAD*4)      // 34816

__global__ __launch_bounds__(128) void k_main7(
        const float* __restrict__ bias,
        float* __restrict__ out) {
    extern __shared__ char sm[];
    uint32_t* vh = (uint32_t*)(sm + SM_VH);
    uint32_t* vl = (uint32_t*)(sm + SM_VL);

    const int tid = threadIdx.x;
    const int bx = blockIdx.x;
    const int h = bx >> 1;
    const int wbase = (bx & 1) << 6;
    const int b = blockIdx.y;
    const int warp = tid >> 5;
    const int lane = tid & 31;
    const int g = lane >> 2;          // groupID 0..7
    const int tig = lane & 3;         // thread-in-group
    const int pb = warp << 4;         // 16-px band per warp
    const float* xb = g_xm + ((size_t)b << 20);

    float d[8][4];
#pragma unroll
    for (int n = 0; n < 8; n++)
#pragma unroll
        for (int j = 0; j < 4; j++) d[n][j] = 0.f;

    const int c4 = tid & 15;
    const int psub = tid >> 4;        // 0..7

    for (int k = 0; k < KK; ++k) {
        const int gibase = ((b*KK + k) << 14) + (h << 7) + wbase;

        // gather + tf32 split: task (p = i*8 + psub, channels 4c4..4c4+3)
#pragma unroll 4
        for (int i = 0; i < 8; ++i) {
            int p = (i << 3) + psub;
            float4 wt = __ldg(&g_wts[gibase + p]);    // uniform across 16 lanes
            int4   of = __ldg(&g_offs[gibase + p]);
            int cc = c4 << 2;
            float4 A0 = *(const float4*)(xb + ((size_t)of.x << 6) + cc);
            float4 A1 = *(const float4*)(xb + ((size_t)of.y << 6) + cc);
            float4 A2 = *(const float4*)(xb + ((size_t)of.z << 6) + cc);
            float4 A3 = *(const float4*)(xb + ((size_t)of.w << 6) + cc);
            float v0 = wt.x*A0.x + wt.y*A1.x + wt.z*A2.x + wt.w*A3.x;
            float v1 = wt.x*A0.y + wt.y*A1.y + wt.z*A2.y + wt.w*A3.y;
            float v2 = wt.x*A0.z + wt.y*A1.z + wt.z*A2.z + wt.w*A3.z;
            float v3 = wt.x*A0.w + wt.y*A1.w + wt.z*A2.w + wt.w*A3.w;
            uint4 hh, ll;
            hh.x = to_tf32(v0); ll.x = to_tf32(v0 - __uint_as_float(hh.x));
            hh.y = to_tf32(v1); ll.y = to_tf32(v1 - __uint_as_float(hh.y));
            hh.z = to_tf32(v2); ll.z = to_tf32(v2 - __uint_as_float(hh.z));
            hh.w = to_tf32(v3); ll.w = to_tf32(v3 - __uint_as_float(hh.w));
            ((uint4*)vh)[p*17 + c4] = hh;   // row = 68 words = 17 uint4
            ((uint4*)vl)[p*17 + c4] = ll;
        }
        __syncthreads();

        // MMA: 8 ksteps; A frags from smem, B frags pre-packed from gmem
        const uint4* bf = g_bfrag + (k << 11);   // per-k stride = 8*8*32 = 2048 uint4
#pragma unroll 2
        for (int kk = 0; kk < 8; ++kk) {
            const int kb = kk << 3;
            uint32_t ah[4], al[4];
            int r0 = (pb + g)*APAD + kb + tig;
            int r8 = (pb + g + 8)*APAD + kb + tig;
            ah[0] = vh[r0];     ah[1] = vh[r8];
            ah[2] = vh[r0 + 4]; ah[3] = vh[r8 + 4];
            al[0] = vl[r0];     al[1] = vl[r8];
            al[2] = vl[r0 + 4]; al[3] = vl[r8 + 4];
#pragma unroll
            for (int n = 0; n < 8; n++) {
                uint4 f = __ldg(bf + ((kk << 3) + n)*32 + lane);
                uint32_t bh[2] = {f.x, f.y};
                uint32_t bl[2] = {f.z, f.w};
                mma_tf32(d[n], ah, bh);
                mma_tf32(d[n], ah, bl);
                mma_tf32(d[n], al, bh);
            }
        }
        __syncthreads();
    }

    // epilogue: d[n][j]: row = pixel pb+g (+8), col = o = 8n + 2tig (+1)
    float* ob = out + ((size_t)(b*OO) << 14) + (h << 7) + wbase;
    int p0 = pb + g;
#pragma unroll
    for (int n = 0; n < 8; n++) {
        int o0 = (n << 3) + (tig << 1);
        float b0 = __ldg(bias + o0);
        float b1 = __ldg(bias + o0 + 1);
        ob[((size_t)o0       << 14) + p0]     = d[n][0] + b0;
        ob[((size_t)(o0 + 1) << 14) + p0]     = d[n][1] + b1;
        ob[((size_t)o0       << 14) + p0 + 8] = d[n][2] + b0;
        ob[((size_t)(o0 + 1) << 14) + p0 + 8] = d[n][3] + b1;
    }
}

extern "C" void kernel_launch(void* const* d_in, const int* in_sizes, int n_in,
                              void* d_out, int out_size) {
    const float* x_main     = (const float*)d_in[0];
    const float* x_extra    = (const float*)d_in[1];
    const float* pre_offset = (const float*)d_in[2];
    const float* pre_sim    = (const float*)d_in[3];
    const float* weight     = (const float*)d_in[4];
    const float* bias       = (const float*)d_in[5];
    const float* w_om       = (const float*)d_in[6];
    const float* b_om       = (const float*)d_in[7];
    float* out = (float*)d_out;

    cudaFuncSetAttribute(k_main7, cudaFuncAttributeMaxDynamicSharedMemorySize, SM_SZ);

    k_bfrag_prep<<<(KK*8*8*32 + 255)/256, 256>>>(weight);
    k_wom_prep<<<(2*32*9*28 + 255)/256, 256>>>(w_om);

    dim3 gt(HW/64, BB);
    k_xm_transpose<<<gt, 256>>>(x_main);

    dim3 g1(WW/16, HH/16, BB);
    k_offset3<<<g1, 128>>>(x_extra, pre_offset, pre_sim, b_om);

    dim3 g2(HH*2, BB);
    k_main7<<<g2, 128, SM_SZ>>>(bias, out);
}